// round 16
// baseline (speedup 1.0000x reference)
#include <cuda_runtime.h>

// ---------------- static scratch (no allocation allowed) ----------------
#define NMAX 50048
#define FMAX 128
#define CAP  96          // max in-degree capacity (data max ~45 incl. self-loop)

__device__ int   d_cnt[NMAX];
__device__ int   d_bucket[NMAX * CAP];        // 19.2 MB
__device__ float d_HA[NMAX * FMAX];
__device__ float d_HB[NMAX * FMAX];
__device__ float d_asrc[NMAX];
__device__ float d_adst[NMAX];
__device__ float d_bn0[32 * 256];    // 32 shadow copies: [s][0:128)=sum, [s][128:256)=sumsq
__device__ float d_bn1[32 * 256];
__device__ float d_pooled[2048 * 64];

#define LOG2E 1.44269504f

__device__ __forceinline__ float leaky(float x, float s) { return x > 0.f ? x : s * x; }

__device__ __forceinline__ float ex2(float x) {
    float r;
    asm("ex2.approx.ftz.f32 %0, %1;" : "=f"(r) : "f"(x));
    return r;
}

__device__ __forceinline__ void cp_async16(float* dst, const float* src, int sz) {
    unsigned d = (unsigned)__cvta_generic_to_shared(dst);
    asm volatile("cp.async.cg.shared.global [%0], [%1], 16, %2;\n" :: "r"(d), "l"(src), "r"(sz));
}
__device__ __forceinline__ void cp_commit() { asm volatile("cp.async.commit_group;\n" ::: "memory"); }
template <int NN>
__device__ __forceinline__ void cp_wait() { asm volatile("cp.async.wait_group %0;\n" :: "n"(NN) : "memory"); }

// ---------------- pipelined GEMM (+optional fused bucket-build blocks) ----------
// Blocks [0,GB): Y = affine(X) @ W + colBias; asrc/adst = (Y·a_s, Y·a_d) * LOG2E
// Blocks [GB,grid): grid-stride bucket fill over E edges + N self-loops + PZ pooled zeros
template <int DIN, int DOUT, int ROWS>
__global__ __launch_bounds__(256) void gemm_att(
    const float* __restrict__ X, const float* __restrict__ W,
    const float* __restrict__ bnPrev, const float* __restrict__ gamma,
    const float* __restrict__ beta, float* __restrict__ bnNext,
    const float* __restrict__ a_s, const float* __restrict__ a_d,
    float* __restrict__ Y, float* __restrict__ asrc, float* __restrict__ adst, int N,
    int GB,
    const int* __restrict__ ei, int E, int* cnt, int* bucket, float* pooled, int PZ)
{
    constexpr int KC  = 32;
    constexpr int NCH = DIN / KC;
    constexpr int TX  = DOUT / 8;
    constexpr int TY  = 256 / TX;
    constexpr int RT  = ROWS / TY;

    int tid = threadIdx.x;

    // ---------- bucket-builder blocks ----------
    if (blockIdx.x >= GB) {
        int nb = gridDim.x - GB;
        int total = E + N + PZ;
        for (int i = (blockIdx.x - GB) * 256 + tid; i < total; i += nb * 256) {
            if (i < E) {
                int s = ei[i], d = ei[E + i];
                int p = atomicAdd(&cnt[d], 1);
                if (p < CAP) bucket[d * CAP + p] = s;
            } else if (i < E + N) {
                int n = i - E;
                int p = atomicAdd(&cnt[n], 1);       // self-loop
                if (p < CAP) bucket[n * CAP + p] = n;
            } else {
                pooled[i - E - N] = 0.f;
            }
        }
        return;
    }

    extern __shared__ float sm[];
    float* sW  = sm;                       // DIN*DOUT (scaled weights)
    float* sX  = sW + DIN * DOUT;          // 2 * ROWS * 32  (XOR-swizzled)
    float* sSc = sX + 2 * ROWS * 32;       // DIN
    float* sSh = sSc + DIN;                // DIN
    float* sCB = sSh + DIN;                // DOUT
    float* red = sCB + DOUT;               // 256

    int tx = tid % TX, ty = tid / TX;
    int ntiles = (N + ROWS - 1) / ROWS;

    auto issue = [&](int tile, int ch, int buf) {
        constexpr int SEGS = ROWS * (KC / 4);   // 16B segments per chunk
        int nodeBase = tile * ROWS;
        float* xb = sX + buf * ROWS * 32;
#pragma unroll
        for (int it = 0; it < SEGS / 256; it++) {
            int idx = it * 256 + tid;
            int r = idx >> 3;                    // 8 segs per row
            int s = idx & 7;
            int n = nodeBase + r;
            int ssw = s ^ ((r / RT) & 7);        // swizzle keyed by owner-ty
            const float* src = X + (size_t)(n < N ? n : 0) * DIN + ch * KC + s * 4;
            cp_async16(xb + r * 32 + ssw * 4, src, (n < N) ? 16 : 0);
        }
        cp_commit();
    };

    // prefetch first chunk — overlaps with the prologue below
    int ptile = blockIdx.x, pch = 0;
    issue(ptile, pch, 0);
    if (++pch == NCH) { pch = 0; ptile += GB; }

    // ---- prologue: BN scale/shift, W preload, colBias, W scaling ----
    for (int j = tid; j < DIN; j += 256) {
        if (bnPrev) {
            float s = 0.f, q = 0.f;
#pragma unroll
            for (int w = 0; w < 32; w++) {
                s += bnPrev[w * 256 + j];
                q += bnPrev[w * 256 + 128 + j];
            }
            float invN = 1.f / (float)N;
            float mu = s * invN;
            float var = q * invN - mu * mu;
            float sc = gamma[j] * rsqrtf(var + 1e-5f);
            sSc[j] = sc; sSh[j] = beta[j] - mu * sc;
        } else { sSc[j] = 1.f; sSh[j] = 0.f; }
    }
    if (blockIdx.x == 0)
        for (int i = tid; i < 32 * 256; i += 256) bnNext[i] = 0.f;
    for (int i = tid; i < DIN * DOUT; i += 256) sW[i] = W[i];
    __syncthreads();
    {
        constexpr int GG = 256 / DOUT;
        constexpr int KT = DIN / GG;
        int c = tid % DOUT, g = tid / DOUT;
        float p = 0.f;
        for (int k = g * KT; k < (g + 1) * KT; k++) p += sSh[k] * sW[k * DOUT + c];
        red[tid] = p;
    }
    __syncthreads();
    if (tid < DOUT) {
        constexpr int GG = 256 / DOUT;
        float p = 0.f;
#pragma unroll
        for (int g = 0; g < GG; g++) p += red[g * DOUT + tid];
        sCB[tid] = p;
    }
    for (int i = tid; i < DIN * DOUT; i += 256) sW[i] *= sSc[i / DOUT];
    __syncthreads();

    // attention vectors pre-scaled by LOG2E so agg can use raw exp2
    float av_s[8], av_d[8], cb[8];
#pragma unroll
    for (int c = 0; c < 8; c++) {
        av_s[c] = a_s[tx * 8 + c] * LOG2E;
        av_d[c] = a_d[tx * 8 + c] * LOG2E;
        cb[c]   = sCB[tx * 8 + c];
    }

    // ---- main pipelined loop ----
    int buf = 0;
    int tysw4 = (ty & 7) * 4;
    for (int tile = blockIdx.x; tile < ntiles; tile += GB) {
        float acc[RT][8];
#pragma unroll
        for (int r = 0; r < RT; r++)
#pragma unroll
            for (int c = 0; c < 8; c++) acc[r][c] = 0.f;

        for (int ch = 0; ch < NCH; ch++) {
            if (ptile < ntiles) {
                issue(ptile, pch, buf ^ 1);
                if (++pch == NCH) { pch = 0; ptile += GB; }
                cp_wait<1>();
            } else {
                cp_wait<0>();
            }
            __syncthreads();

            const float* xb = sX + buf * ROWS * 32 + ty * RT * 32;
            const float* wb = sW + ch * KC * DOUT + tx * 8;
#pragma unroll 8
            for (int k = 0; k < KC; k++) {
                int koff = (((k >> 2) * 4) ^ tysw4) + (k & 3);
                float4 wa = *(const float4*)(wb + k * DOUT);
                float4 wv = *(const float4*)(wb + k * DOUT + 4);
                float xv[RT];
#pragma unroll
                for (int r = 0; r < RT; r++) xv[r] = xb[r * 32 + koff];
#pragma unroll
                for (int r = 0; r < RT; r++) {
                    acc[r][0] += xv[r] * wa.x; acc[r][1] += xv[r] * wa.y;
                    acc[r][2] += xv[r] * wa.z; acc[r][3] += xv[r] * wa.w;
                    acc[r][4] += xv[r] * wv.x; acc[r][5] += xv[r] * wv.y;
                    acc[r][6] += xv[r] * wv.z; acc[r][7] += xv[r] * wv.w;
                }
            }
            buf ^= 1;
            __syncthreads();   // protect just-read buffer before it is refilled
        }

        // epilogue: colBias, attention dots, store
#pragma unroll
        for (int r = 0; r < RT; r++) {
            int n = tile * ROWS + ty * RT + r;
            float ps = 0.f, pd = 0.f;
#pragma unroll
            for (int c = 0; c < 8; c++) {
                acc[r][c] += cb[c];
                ps += acc[r][c] * av_s[c];
                pd += acc[r][c] * av_d[c];
            }
#pragma unroll
            for (int o = TX >> 1; o; o >>= 1) {
                ps += __shfl_xor_sync(0xffffffffu, ps, o);
                pd += __shfl_xor_sync(0xffffffffu, pd, o);
            }
            if (n < N) {
                if (tx == 0) { asrc[n] = ps; adst[n] = pd; }
                *(float4*)&Y[(size_t)n * DOUT + tx * 8] =
                    make_float4(acc[r][0], acc[r][1], acc[r][2], acc[r][3]);
                *(float4*)&Y[(size_t)n * DOUT + tx * 8 + 4] =
                    make_float4(acc[r][4], acc[r][5], acc[r][6], acc[r][7]);
            }
        }
    }
}

// ---------------- lane-parallel softmax aggregation + BN stats, warp per dst ---------
// Batch of 32 edges: lane j computes w_j (ONE exp2/MUFU per 32 edges per warp),
// then (idx,w) are shuffle-broadcast for the gather. Σw via end warp-reduce.
template <int DOUT>
__global__ __launch_bounds__(128) void agg_bn(
    const float* __restrict__ h, const float* __restrict__ asrc,
    const float* __restrict__ adst, const int* __restrict__ cnt,
    const int* __restrict__ bucket, const float* __restrict__ bias,
    float* __restrict__ out, float* __restrict__ bnbuf, int N)
{
    constexpr int F = DOUT / 32;
    __shared__ float sS[4][DOUT];
    __shared__ float sQ[4][DOUT];
    int warp = threadIdx.x >> 5, lane = threadIdx.x & 31;
    int n = blockIdx.x * 4 + warp;

    float vout[F];
#pragma unroll
    for (int f = 0; f < F; f++) vout[f] = 0.f;

    if (n < N) {
        const int* brow = bucket + n * CAP;
        int c = cnt[n];
        float ad = adst[n];
        const float* hl = h + lane;          // lane-offset base

        float sp = 0.f;                      // per-lane partial of Σw
        float acc[F];
#pragma unroll
        for (int f = 0; f < F; f++) acc[f] = 0.f;

        for (int base = 0; base < c; base += 32) {
            int rem = c - base;
            int iters = rem < 32 ? rem : 32;

            // lane-parallel weight phase: one exp2 per 32 edges
            int   myoff = 0;
            float myw = 0.f;
            if (lane < iters) {
                int idx = brow[base + lane];
                float y = asrc[idx] + ad;
                myw = ex2(fmaxf(y, 0.2f * y));
                myoff = idx * DOUT;
            }
            sp += myw;

            // gather phase: broadcast (off, w) from each lane
            int j = 0;
            for (; j + 4 <= iters; j += 4) {
                int   o0 = __shfl_sync(0xffffffffu, myoff, j);
                int   o1 = __shfl_sync(0xffffffffu, myoff, j + 1);
                int   o2 = __shfl_sync(0xffffffffu, myoff, j + 2);
                int   o3 = __shfl_sync(0xffffffffu, myoff, j + 3);
                float w0 = __shfl_sync(0xffffffffu, myw, j);
                float w1 = __shfl_sync(0xffffffffu, myw, j + 1);
                float w2 = __shfl_sync(0xffffffffu, myw, j + 2);
                float w3 = __shfl_sync(0xffffffffu, myw, j + 3);
#pragma unroll
                for (int f = 0; f < F; f++) {
                    acc[f] += w0 * hl[o0 + 32 * f] + w1 * hl[o1 + 32 * f]
                            + w2 * hl[o2 + 32 * f] + w3 * hl[o3 + 32 * f];
                }
            }
            for (; j < iters; j++) {
                int   o0 = __shfl_sync(0xffffffffu, myoff, j);
                float w0 = __shfl_sync(0xffffffffu, myw, j);
#pragma unroll
                for (int f = 0; f < F; f++) acc[f] += w0 * hl[o0 + 32 * f];
            }
        }

        // Σw: warp reduce per-lane partials
#pragma unroll
        for (int o = 16; o; o >>= 1) sp += __shfl_xor_sync(0xffffffffu, sp, o);
        float inv = 1.f / sp;                // self-loop guarantees sp > 0

#pragma unroll
        for (int f = 0; f < F; f++) {
            float v = acc[f] * inv + bias[lane + 32 * f];
            v = fmaxf(v, 0.01f * v);
            out[(size_t)n * DOUT + lane + 32 * f] = v;
            vout[f] = v;
        }
    }

    // fused BN stats: block reduce (4 warps) then 32-shadow global atomics
#pragma unroll
    for (int f = 0; f < F; f++) {
        sS[warp][lane + 32 * f] = vout[f];
        sQ[warp][lane + 32 * f] = vout[f] * vout[f];
    }
    __syncthreads();
    int shadow = (blockIdx.x & 31) * 256;
    for (int j = threadIdx.x; j < DOUT; j += 128) {
        float a = 0.f, b = 0.f;
#pragma unroll
        for (int w = 0; w < 4; w++) { a += sS[w][j]; b += sQ[w][j]; }
        atomicAdd(&bnbuf[shadow + j], a);
        atomicAdd(&bnbuf[shadow + 128 + j], b);
    }
}

// ---------------- pooling: inline layer-4 BN affine; also re-zeroes cnt -------------
__global__ void pool_kernel(const float* __restrict__ act, const float* __restrict__ bnbuf,
                            const float* __restrict__ g, const float* __restrict__ be,
                            const int* __restrict__ batch, float* pooled, int* cnt, int N)
{
    int j = threadIdx.x;            // 0..63
    float s = 0.f, q = 0.f;
#pragma unroll
    for (int w = 0; w < 32; w++) { s += bnbuf[w * 256 + j]; q += bnbuf[w * 256 + 128 + j]; }
    float invN = 1.f / (float)N;
    float mu = s * invN;
    float var = q * invN - mu * mu;
    float sc = g[j] * rsqrtf(var + 1e-5f);
    float sh = be[j] - mu * sc;

    int n0 = blockIdx.x * 32;
    int n1 = n0 + 32; if (n1 > N) n1 = N;
    float acc = 0.f;
    int cur = -1;
    for (int n = n0; n < n1; n++) {
        int b = batch[n];
        if (b != cur) {
            if (cur >= 0) atomicAdd(&pooled[cur * 64 + j], acc);
            cur = b; acc = 0.f;
        }
        acc += act[(size_t)n * 64 + j] * sc + sh;
    }
    if (cur >= 0) atomicAdd(&pooled[cur * 64 + j], acc);

    // restore cnt[] to zero for the next replay (deterministic state)
    int z = blockIdx.x * 64 + threadIdx.x;
    if (z < NMAX) cnt[z] = 0;
}

// ---------------- final MLP + sigmoid ----------------
__global__ void mlp_kernel(const float* __restrict__ pooled, const float* __restrict__ Wf,
                           const float* __restrict__ bf, const float* __restrict__ Wc,
                           const float* __restrict__ bc, float* __restrict__ out, int G)
{
    int g = blockIdx.x;
    __shared__ float p[64];
    __shared__ float z[32];
    int t = threadIdx.x;            // 64 threads
    p[t] = pooled[g * 64 + t];
    __syncthreads();
    if (t < 32) {
        float a = bf[t];
#pragma unroll 8
        for (int k = 0; k < 64; k++) a += p[k] * Wf[k * 32 + t];
        z[t] = leaky(a, 0.01f);
    }
    __syncthreads();
    if (t < 8) {
        float a = bc[t];
#pragma unroll
        for (int jj = 0; jj < 32; jj++) a += z[jj] * Wc[jj * 8 + t];
        out[g * 8 + t] = 1.f / (1.f + expf(-a));
    }
}

// ---------------- host launcher (10 launches; slot 4 = agg1 for ncu) ----------------
extern "C" void kernel_launch(void* const* d_in, const int* in_sizes, int n_in,
                              void* d_out, int out_size)
{
    const float* x     = (const float*)d_in[0];
    const int*   ei    = (const int*)d_in[1];
    const int*   batch = (const int*)d_in[2];
    int N = in_sizes[2];
    int E = in_sizes[1] / 2;
    int G = out_size / 8;
    float* out = (float*)d_out;

    const float *W[4], *As[4], *Ad[4], *B[4], *Gm[4], *Be[4];
    for (int i = 0; i < 4; i++) {
        int base = 3 + 6 * i;
        W[i]  = (const float*)d_in[base + 0];
        As[i] = (const float*)d_in[base + 1];
        Ad[i] = (const float*)d_in[base + 2];
        B[i]  = (const float*)d_in[base + 3];
        Gm[i] = (const float*)d_in[base + 4];
        Be[i] = (const float*)d_in[base + 5];
    }
    const float* Wf = (const float*)d_in[27];
    const float* bf = (const float*)d_in[28];
    const float* Wc = (const float*)d_in[29];
    const float* bc = (const float*)d_in[30];

    int *cnt, *bucket;
    float *HA, *HB, *asrc, *adst, *bn0, *bn1, *pooled;
    cudaGetSymbolAddress((void**)&cnt,    d_cnt);
    cudaGetSymbolAddress((void**)&bucket, d_bucket);
    cudaGetSymbolAddress((void**)&HA,     d_HA);
    cudaGetSymbolAddress((void**)&HB,     d_HB);
    cudaGetSymbolAddress((void**)&asrc,   d_asrc);
    cudaGetSymbolAddress((void**)&adst,   d_adst);
    cudaGetSymbolAddress((void**)&bn0,    d_bn0);
    cudaGetSymbolAddress((void**)&bn1,    d_bn1);
    cudaGetSymbolAddress((void**)&pooled, d_pooled);

    int nwb = (N + 3) / 4;          // 128-thread blocks, 4 warps = 4 nodes each
    int PZ = G * 64;

    auto smemB = [](int DIN, int DOUT, int ROWS) {
        return (DIN * DOUT + 2 * ROWS * 32 + 2 * DIN + DOUT + 256) * 4;
    };
    int sm0 = smemB(128, 32, 128);
    int sm1 = smemB(32, 64, 128);
    int sm2 = smemB(64, 128, 64);
    int sm3 = smemB(128, 64, 128);
    cudaFuncSetAttribute(gemm_att<128, 32, 128>, cudaFuncAttributeMaxDynamicSharedMemorySize, sm0);
    cudaFuncSetAttribute(gemm_att<32, 64, 128>,  cudaFuncAttributeMaxDynamicSharedMemorySize, sm1);
    cudaFuncSetAttribute(gemm_att<64, 128, 64>,  cudaFuncAttributeMaxDynamicSharedMemorySize, sm2);
    cudaFuncSetAttribute(gemm_att<128, 64, 128>, cudaFuncAttributeMaxDynamicSharedMemorySize, sm3);

    auto gsz = [](int ntiles) { return ntiles < 444 ? ntiles : 444; };
    int nt128 = (N + 127) / 128;
    int nt64  = (N + 63) / 64;

    // 1: layer-0 GEMM fused with bucket build + pooled zero.
    {
        int GB = nt128 < 296 ? nt128 : 296;
        gemm_att<128, 32, 128><<<GB + 296, 256, sm0>>>(
            x, W[0], nullptr, nullptr, nullptr, bn0, As[0], Ad[0], HA, asrc, adst, N,
            GB, ei, E, cnt, bucket, pooled, PZ);
    }

    // 2: layer-0 aggregation
    agg_bn<32><<<nwb, 128>>>(HA, asrc, adst, cnt, bucket, B[0], HB, bn0, N);

    // 3: layer 1 GEMM: 32 -> 64
    gemm_att<32, 64, 128><<<gsz(nt128), 256, sm1>>>(
        HB, W[1], bn0, Gm[0], Be[0], bn1, As[1], Ad[1], HA, asrc, adst, N,
        gsz(nt128), nullptr, 0, nullptr, nullptr, nullptr, 0);

    // 4 (ncu slot): layer-1 aggregation
    agg_bn<64><<<nwb, 128>>>(HA, asrc, adst, cnt, bucket, B[1], HB, bn1, N);

    // layer 2: 64 -> 128
    gemm_att<64, 128, 64><<<gsz(nt64), 256, sm2>>>(
        HB, W[2], bn1, Gm[1], Be[1], bn0, As[2], Ad[2], HA, asrc, adst, N,
        gsz(nt64), nullptr, 0, nullptr, nullptr, nullptr, 0);
    agg_bn<128><<<nwb, 128>>>(HA, asrc, adst, cnt, bucket, B[2], HB, bn0, N);

    // layer 3: 128 -> 64
    gemm_att<128, 64, 128><<<gsz(nt128), 256, sm3>>>(
        HB, W[3], bn0, Gm[2], Be[2], bn1, As[3], Ad[3], HA, asrc, adst, N,
        gsz(nt128), nullptr, 0, nullptr, nullptr, nullptr, 0);
    agg_bn<64><<<nwb, 128>>>(HA, asrc, adst, cnt, bucket, B[3], HB, bn1, N);

    // pooling (BN3 affine inline; also re-zeroes cnt)
    pool_kernel<<<(N + 31) / 32, 64>>>(HB, bn1, Gm[3], Be[3], batch, pooled, cnt, N);

    // final MLP + sigmoid
    mlp_kernel<<<G, 64>>>(pooled, Wf, bf, Wc, bc, out, G);
}

// round 17
// speedup vs baseline: 1.0702x; 1.0702x over previous
#include <cuda_runtime.h>

// ---------------- static scratch (no allocation allowed) ----------------
#define NMAX 50048
#define FMAX 128
#define CAP  96          // max in-degree capacity (data max ~45 incl. self-loop)

__device__ int   d_cnt[NMAX];
__device__ int   d_bucket[NMAX * CAP];        // 19.2 MB
__device__ float d_HA[NMAX * FMAX];
__device__ float d_HB[NMAX * FMAX];
__device__ float d_asrc[NMAX];
__device__ float d_adst[NMAX];
__device__ float d_bn0[32 * 256];    // 32 shadow copies: [s][0:128)=sum, [s][128:256)=sumsq
__device__ float d_bn1[32 * 256];
__device__ float d_pooled[2048 * 64];

#define LOG2E 1.44269504f

__device__ __forceinline__ float leaky(float x, float s) { return x > 0.f ? x : s * x; }

__device__ __forceinline__ float ex2(float x) {
    float r;
    asm("ex2.approx.ftz.f32 %0, %1;" : "=f"(r) : "f"(x));
    return r;
}

__device__ __forceinline__ void cp_async16(float* dst, const float* src, int sz) {
    unsigned d = (unsigned)__cvta_generic_to_shared(dst);
    asm volatile("cp.async.cg.shared.global [%0], [%1], 16, %2;\n" :: "r"(d), "l"(src), "r"(sz));
}
__device__ __forceinline__ void cp_commit() { asm volatile("cp.async.commit_group;\n" ::: "memory"); }
template <int NN>
__device__ __forceinline__ void cp_wait() { asm volatile("cp.async.wait_group %0;\n" :: "n"(NN) : "memory"); }

// ---------------- pipelined GEMM (+optional fused bucket-build blocks) ----------
// Blocks [0,GB): Y = affine(X) @ W + colBias; asrc/adst = (Y·a_s, Y·a_d) * LOG2E
// Blocks [GB,grid): grid-stride bucket fill over E edges + N self-loops + PZ pooled zeros
template <int DIN, int DOUT, int ROWS>
__global__ __launch_bounds__(256) void gemm_att(
    const float* __restrict__ X, const float* __restrict__ W,
    const float* __restrict__ bnPrev, const float* __restrict__ gamma,
    const float* __restrict__ beta, float* __restrict__ bnNext,
    const float* __restrict__ a_s, const float* __restrict__ a_d,
    float* __restrict__ Y, float* __restrict__ asrc, float* __restrict__ adst, int N,
    int GB,
    const int* __restrict__ ei, int E, int* cnt, int* bucket, float* pooled, int PZ)
{
    constexpr int KC  = 32;
    constexpr int NCH = DIN / KC;
    constexpr int TX  = DOUT / 8;
    constexpr int TY  = 256 / TX;
    constexpr int RT  = ROWS / TY;

    int tid = threadIdx.x;

    // ---------- bucket-builder blocks ----------
    if (blockIdx.x >= GB) {
        int nb = gridDim.x - GB;
        int total = E + N + PZ;
        for (int i = (blockIdx.x - GB) * 256 + tid; i < total; i += nb * 256) {
            if (i < E) {
                int s = ei[i], d = ei[E + i];
                int p = atomicAdd(&cnt[d], 1);
                if (p < CAP) bucket[d * CAP + p] = s;
            } else if (i < E + N) {
                int n = i - E;
                int p = atomicAdd(&cnt[n], 1);       // self-loop
                if (p < CAP) bucket[n * CAP + p] = n;
            } else {
                pooled[i - E - N] = 0.f;
            }
        }
        return;
    }

    extern __shared__ float sm[];
    float* sW  = sm;                       // DIN*DOUT (scaled weights)
    float* sX  = sW + DIN * DOUT;          // 2 * ROWS * 32  (XOR-swizzled)
    float* sSc = sX + 2 * ROWS * 32;       // DIN
    float* sSh = sSc + DIN;                // DIN
    float* sCB = sSh + DIN;                // DOUT
    float* red = sCB + DOUT;               // 256

    int tx = tid % TX, ty = tid / TX;
    int ntiles = (N + ROWS - 1) / ROWS;

    auto issue = [&](int tile, int ch, int buf) {
        constexpr int SEGS = ROWS * (KC / 4);   // 16B segments per chunk
        int nodeBase = tile * ROWS;
        float* xb = sX + buf * ROWS * 32;
#pragma unroll
        for (int it = 0; it < SEGS / 256; it++) {
            int idx = it * 256 + tid;
            int r = idx >> 3;                    // 8 segs per row
            int s = idx & 7;
            int n = nodeBase + r;
            int ssw = s ^ ((r / RT) & 7);        // swizzle keyed by owner-ty
            const float* src = X + (size_t)(n < N ? n : 0) * DIN + ch * KC + s * 4;
            cp_async16(xb + r * 32 + ssw * 4, src, (n < N) ? 16 : 0);
        }
        cp_commit();
    };

    // prefetch first chunk — overlaps with the prologue below
    int ptile = blockIdx.x, pch = 0;
    issue(ptile, pch, 0);
    if (++pch == NCH) { pch = 0; ptile += GB; }

    // ---- prologue: BN scale/shift, W preload, colBias, W scaling ----
    for (int j = tid; j < DIN; j += 256) {
        if (bnPrev) {
            float s = 0.f, q = 0.f;
#pragma unroll
            for (int w = 0; w < 32; w++) {
                s += bnPrev[w * 256 + j];
                q += bnPrev[w * 256 + 128 + j];
            }
            float invN = 1.f / (float)N;
            float mu = s * invN;
            float var = q * invN - mu * mu;
            float sc = gamma[j] * rsqrtf(var + 1e-5f);
            sSc[j] = sc; sSh[j] = beta[j] - mu * sc;
        } else { sSc[j] = 1.f; sSh[j] = 0.f; }
    }
    if (blockIdx.x == 0)
        for (int i = tid; i < 32 * 256; i += 256) bnNext[i] = 0.f;
    for (int i = tid; i < DIN * DOUT; i += 256) sW[i] = W[i];
    __syncthreads();
    {
        constexpr int GG = 256 / DOUT;
        constexpr int KT = DIN / GG;
        int c = tid % DOUT, g = tid / DOUT;
        float p = 0.f;
        for (int k = g * KT; k < (g + 1) * KT; k++) p += sSh[k] * sW[k * DOUT + c];
        red[tid] = p;
    }
    __syncthreads();
    if (tid < DOUT) {
        constexpr int GG = 256 / DOUT;
        float p = 0.f;
#pragma unroll
        for (int g = 0; g < GG; g++) p += red[g * DOUT + tid];
        sCB[tid] = p;
    }
    for (int i = tid; i < DIN * DOUT; i += 256) sW[i] *= sSc[i / DOUT];
    __syncthreads();

    // attention vectors pre-scaled by LOG2E so agg can use raw exp2
    float av_s[8], av_d[8], cb[8];
#pragma unroll
    for (int c = 0; c < 8; c++) {
        av_s[c] = a_s[tx * 8 + c] * LOG2E;
        av_d[c] = a_d[tx * 8 + c] * LOG2E;
        cb[c]   = sCB[tx * 8 + c];
    }

    // ---- main pipelined loop ----
    int buf = 0;
    int tysw4 = (ty & 7) * 4;
    for (int tile = blockIdx.x; tile < ntiles; tile += GB) {
        float acc[RT][8];
#pragma unroll
        for (int r = 0; r < RT; r++)
#pragma unroll
            for (int c = 0; c < 8; c++) acc[r][c] = 0.f;

        for (int ch = 0; ch < NCH; ch++) {
            if (ptile < ntiles) {
                issue(ptile, pch, buf ^ 1);
                if (++pch == NCH) { pch = 0; ptile += GB; }
                cp_wait<1>();
            } else {
                cp_wait<0>();
            }
            __syncthreads();

            const float* xb = sX + buf * ROWS * 32 + ty * RT * 32;
            const float* wb = sW + ch * KC * DOUT + tx * 8;
#pragma unroll 8
            for (int k = 0; k < KC; k++) {
                int koff = (((k >> 2) * 4) ^ tysw4) + (k & 3);
                float4 wa = *(const float4*)(wb + k * DOUT);
                float4 wv = *(const float4*)(wb + k * DOUT + 4);
                float xv[RT];
#pragma unroll
                for (int r = 0; r < RT; r++) xv[r] = xb[r * 32 + koff];
#pragma unroll
                for (int r = 0; r < RT; r++) {
                    acc[r][0] += xv[r] * wa.x; acc[r][1] += xv[r] * wa.y;
                    acc[r][2] += xv[r] * wa.z; acc[r][3] += xv[r] * wa.w;
                    acc[r][4] += xv[r] * wv.x; acc[r][5] += xv[r] * wv.y;
                    acc[r][6] += xv[r] * wv.z; acc[r][7] += xv[r] * wv.w;
                }
            }
            buf ^= 1;
            __syncthreads();   // protect just-read buffer before it is refilled
        }

        // epilogue: colBias, attention dots, store
#pragma unroll
        for (int r = 0; r < RT; r++) {
            int n = tile * ROWS + ty * RT + r;
            float ps = 0.f, pd = 0.f;
#pragma unroll
            for (int c = 0; c < 8; c++) {
                acc[r][c] += cb[c];
                ps += acc[r][c] * av_s[c];
                pd += acc[r][c] * av_d[c];
            }
#pragma unroll
            for (int o = TX >> 1; o; o >>= 1) {
                ps += __shfl_xor_sync(0xffffffffu, ps, o);
                pd += __shfl_xor_sync(0xffffffffu, pd, o);
            }
            if (n < N) {
                if (tx == 0) { asrc[n] = ps; adst[n] = pd; }
                *(float4*)&Y[(size_t)n * DOUT + tx * 8] =
                    make_float4(acc[r][0], acc[r][1], acc[r][2], acc[r][3]);
                *(float4*)&Y[(size_t)n * DOUT + tx * 8 + 4] =
                    make_float4(acc[r][4], acc[r][5], acc[r][6], acc[r][7]);
            }
        }
    }
}

// ---------------- smem-staged softmax aggregation + BN stats, warp per dst ---------
// Weight phase (lane-parallel, one exp2 per 32 edges) writes packed (off,w) float2
// pairs to a per-warp smem strip; gather phase reads them via LDS at static
// addresses so the h-gather LDGs can issue deeply ahead.
template <int DOUT>
__global__ __launch_bounds__(128) void agg_bn(
    const float* __restrict__ h, const float* __restrict__ asrc,
    const float* __restrict__ adst, const int* __restrict__ cnt,
    const int* __restrict__ bucket, const float* __restrict__ bias,
    float* __restrict__ out, float* __restrict__ bnbuf, int N)
{
    constexpr int F = DOUT / 32;
    __shared__ float2 sPair[4][CAP];      // per-warp (offset,weight) strip
    __shared__ float sS[4][DOUT];
    __shared__ float sQ[4][DOUT];
    int warp = threadIdx.x >> 5, lane = threadIdx.x & 31;
    int n = blockIdx.x * 4 + warp;

    float vout[F];
#pragma unroll
    for (int f = 0; f < F; f++) vout[f] = 0.f;

    if (n < N) {
        const int* brow = bucket + n * CAP;
        int c = cnt[n];
        if (c > CAP) c = CAP;
        float ad = adst[n];
        const float* hl = h + lane;          // lane-offset base

        // ---- weight phase: lane j handles edge base+j ----
        float sp = 0.f;                      // per-lane partial of Σw
        for (int base = 0; base < c; base += 32) {
            if (base + lane < c) {
                int idx = brow[base + lane];
                float y = asrc[idx] + ad;
                float w = ex2(fmaxf(y, 0.2f * y));
                sp += w;
                sPair[warp][base + lane] = make_float2(__int_as_float(idx * DOUT), w);
            }
        }
        __syncwarp();

        // ---- gather phase: LDS pairs at static addresses, deep LDG pipeline ----
        float acc[F];
#pragma unroll
        for (int f = 0; f < F; f++) acc[f] = 0.f;

        const float2* sp2 = sPair[warp];
        int i = 0;
        for (; i + 4 <= c; i += 4) {
            float2 p0 = sp2[i],     p1 = sp2[i + 1];
            float2 p2 = sp2[i + 2], p3 = sp2[i + 3];
            int o0 = __float_as_int(p0.x), o1 = __float_as_int(p1.x);
            int o2 = __float_as_int(p2.x), o3 = __float_as_int(p3.x);
#pragma unroll
            for (int f = 0; f < F; f++) {
                acc[f] += p0.y * hl[o0 + 32 * f] + p1.y * hl[o1 + 32 * f]
                        + p2.y * hl[o2 + 32 * f] + p3.y * hl[o3 + 32 * f];
            }
        }
        for (; i < c; i++) {
            float2 p0 = sp2[i];
            int o0 = __float_as_int(p0.x);
#pragma unroll
            for (int f = 0; f < F; f++) acc[f] += p0.y * hl[o0 + 32 * f];
        }

        // Σw: warp reduce per-lane partials
#pragma unroll
        for (int o = 16; o; o >>= 1) sp += __shfl_xor_sync(0xffffffffu, sp, o);
        float inv = 1.f / sp;                // self-loop guarantees sp > 0

#pragma unroll
        for (int f = 0; f < F; f++) {
            float v = acc[f] * inv + bias[lane + 32 * f];
            v = fmaxf(v, 0.01f * v);
            out[(size_t)n * DOUT + lane + 32 * f] = v;
            vout[f] = v;
        }
    }

    // fused BN stats: block reduce (4 warps) then 32-shadow global atomics
#pragma unroll
    for (int f = 0; f < F; f++) {
        sS[warp][lane + 32 * f] = vout[f];
        sQ[warp][lane + 32 * f] = vout[f] * vout[f];
    }
    __syncthreads();
    int shadow = (blockIdx.x & 31) * 256;
    for (int j = threadIdx.x; j < DOUT; j += 128) {
        float a = 0.f, b = 0.f;
#pragma unroll
        for (int w = 0; w < 4; w++) { a += sS[w][j]; b += sQ[w][j]; }
        atomicAdd(&bnbuf[shadow + j], a);
        atomicAdd(&bnbuf[shadow + 128 + j], b);
    }
}

// ---------------- pooling: inline layer-4 BN affine; also re-zeroes cnt -------------
__global__ void pool_kernel(const float* __restrict__ act, const float* __restrict__ bnbuf,
                            const float* __restrict__ g, const float* __restrict__ be,
                            const int* __restrict__ batch, float* pooled, int* cnt, int N)
{
    int j = threadIdx.x;            // 0..63
    float s = 0.f, q = 0.f;
#pragma unroll
    for (int w = 0; w < 32; w++) { s += bnbuf[w * 256 + j]; q += bnbuf[w * 256 + 128 + j]; }
    float invN = 1.f / (float)N;
    float mu = s * invN;
    float var = q * invN - mu * mu;
    float sc = g[j] * rsqrtf(var + 1e-5f);
    float sh = be[j] - mu * sc;

    int n0 = blockIdx.x * 32;
    int n1 = n0 + 32; if (n1 > N) n1 = N;
    float acc = 0.f;
    int cur = -1;
    for (int n = n0; n < n1; n++) {
        int b = batch[n];
        if (b != cur) {
            if (cur >= 0) atomicAdd(&pooled[cur * 64 + j], acc);
            cur = b; acc = 0.f;
        }
        acc += act[(size_t)n * 64 + j] * sc + sh;
    }
    if (cur >= 0) atomicAdd(&pooled[cur * 64 + j], acc);

    // restore cnt[] to zero for the next replay (deterministic state)
    int z = blockIdx.x * 64 + threadIdx.x;
    if (z < NMAX) cnt[z] = 0;
}

// ---------------- final MLP + sigmoid ----------------
__global__ void mlp_kernel(const float* __restrict__ pooled, const float* __restrict__ Wf,
                           const float* __restrict__ bf, const float* __restrict__ Wc,
                           const float* __restrict__ bc, float* __restrict__ out, int G)
{
    int g = blockIdx.x;
    __shared__ float p[64];
    __shared__ float z[32];
    int t = threadIdx.x;            // 64 threads
    p[t] = pooled[g * 64 + t];
    __syncthreads();
    if (t < 32) {
        float a = bf[t];
#pragma unroll 8
        for (int k = 0; k < 64; k++) a += p[k] * Wf[k * 32 + t];
        z[t] = leaky(a, 0.01f);
    }
    __syncthreads();
    if (t < 8) {
        float a = bc[t];
#pragma unroll
        for (int jj = 0; jj < 32; jj++) a += z[jj] * Wc[jj * 8 + t];
        out[g * 8 + t] = 1.f / (1.f + expf(-a));
    }
}

// ---------------- host launcher (10 launches; slot 4 = agg1 for ncu) ----------------
extern "C" void kernel_launch(void* const* d_in, const int* in_sizes, int n_in,
                              void* d_out, int out_size)
{
    const float* x     = (const float*)d_in[0];
    const int*   ei    = (const int*)d_in[1];
    const int*   batch = (const int*)d_in[2];
    int N = in_sizes[2];
    int E = in_sizes[1] / 2;
    int G = out_size / 8;
    float* out = (float*)d_out;

    const float *W[4], *As[4], *Ad[4], *B[4], *Gm[4], *Be[4];
    for (int i = 0; i < 4; i++) {
        int base = 3 + 6 * i;
        W[i]  = (const float*)d_in[base + 0];
        As[i] = (const float*)d_in[base + 1];
        Ad[i] = (const float*)d_in[base + 2];
        B[i]  = (const float*)d_in[base + 3];
        Gm[i] = (const float*)d_in[base + 4];
        Be[i] = (const float*)d_in[base + 5];
    }
    const float* Wf = (const float*)d_in[27];
    const float* bf = (const float*)d_in[28];
    const float* Wc = (const float*)d_in[29];
    const float* bc = (const float*)d_in[30];

    int *cnt, *bucket;
    float *HA, *HB, *asrc, *adst, *bn0, *bn1, *pooled;
    cudaGetSymbolAddress((void**)&cnt,    d_cnt);
    cudaGetSymbolAddress((void**)&bucket, d_bucket);
    cudaGetSymbolAddress((void**)&HA,     d_HA);
    cudaGetSymbolAddress((void**)&HB,     d_HB);
    cudaGetSymbolAddress((void**)&asrc,   d_asrc);
    cudaGetSymbolAddress((void**)&adst,   d_adst);
    cudaGetSymbolAddress((void**)&bn0,    d_bn0);
    cudaGetSymbolAddress((void**)&bn1,    d_bn1);
    cudaGetSymbolAddress((void**)&pooled, d_pooled);

    int nwb = (N + 3) / 4;          // 128-thread blocks, 4 warps = 4 nodes each
    int PZ = G * 64;

    auto smemB = [](int DIN, int DOUT, int ROWS) {
        return (DIN * DOUT + 2 * ROWS * 32 + 2 * DIN + DOUT + 256) * 4;
    };
    int sm0 = smemB(128, 32, 128);
    int sm1 = smemB(32, 64, 128);
    int sm2 = smemB(64, 128, 64);
    int sm3 = smemB(128, 64, 128);
    cudaFuncSetAttribute(gemm_att<128, 32, 128>, cudaFuncAttributeMaxDynamicSharedMemorySize, sm0);
    cudaFuncSetAttribute(gemm_att<32, 64, 128>,  cudaFuncAttributeMaxDynamicSharedMemorySize, sm1);
    cudaFuncSetAttribute(gemm_att<64, 128, 64>,  cudaFuncAttributeMaxDynamicSharedMemorySize, sm2);
    cudaFuncSetAttribute(gemm_att<128, 64, 128>, cudaFuncAttributeMaxDynamicSharedMemorySize, sm3);

    auto gsz = [](int ntiles) { return ntiles < 444 ? ntiles : 444; };
    int nt128 = (N + 127) / 128;
    int nt64  = (N + 63) / 64;

    // 1: layer-0 GEMM fused with bucket build + pooled zero.
    {
        int GB = nt128 < 296 ? nt128 : 296;
        gemm_att<128, 32, 128><<<GB + 296, 256, sm0>>>(
            x, W[0], nullptr, nullptr, nullptr, bn0, As[0], Ad[0], HA, asrc, adst, N,
            GB, ei, E, cnt, bucket, pooled, PZ);
    }

    // 2: layer-0 aggregation
    agg_bn<32><<<nwb, 128>>>(HA, asrc, adst, cnt, bucket, B[0], HB, bn0, N);

    // 3: layer 1 GEMM: 32 -> 64
    gemm_att<32, 64, 128><<<gsz(nt128), 256, sm1>>>(
        HB, W[1], bn0, Gm[0], Be[0], bn1, As[1], Ad[1], HA, asrc, adst, N,
        gsz(nt128), nullptr, 0, nullptr, nullptr, nullptr, 0);

    // 4 (ncu slot): layer-1 aggregation
    agg_bn<64><<<nwb, 128>>>(HA, asrc, adst, cnt, bucket, B[1], HB, bn1, N);

    // layer 2: 64 -> 128
    gemm_att<64, 128, 64><<<gsz(nt64), 256, sm2>>>(
        HB, W[2], bn1, Gm[1], Be[1], bn0, As[2], Ad[2], HA, asrc, adst, N,
        gsz(nt64), nullptr, 0, nullptr, nullptr, nullptr, 0);
    agg_bn<128><<<nwb, 128>>>(HA, asrc, adst, cnt, bucket, B[2], HB, bn0, N);

    // layer 3: 128 -> 64
    gemm_att<128, 64, 128><<<gsz(nt128), 256, sm3>>>(
        HB, W[3], bn0, Gm[2], Be[2], bn1, As[3], Ad[3], HA, asrc, adst, N,
        gsz(nt128), nullptr, 0, nullptr, nullptr, nullptr, 0);
    agg_bn<64><<<nwb, 128>>>(HA, asrc, adst, cnt, bucket, B[3], HB, bn1, N);

    // pooling (BN3 affine inline; also re-zeroes cnt)
    pool_kernel<<<(N + 31) / 32, 64>>>(HB, bn1, Gm[3], Be[3], batch, pooled, cnt, N);

    // final MLP + sigmoid
    mlp_kernel<<<G, 64>>>(pooled, Wf, bf, Wc, bc, out, G);
}